// round 3
// baseline (speedup 1.0000x reference)
#include <cuda_runtime.h>
#include <math.h>

// Problem constants
#define B_   8
#define S_   1024
#define H_   16
#define DV_  1024
#define LAT_ 1024
#define D_   64          // DQ == DH == 64

// Scratch (allocation-free rule: __device__ globals)
__device__ float g_Q[(size_t)B_ * H_ * S_ * D_];   // [bh, s, d]
__device__ float g_K[(size_t)B_ * H_ * S_ * D_];   // [bh, s, d]
__device__ float g_V[(size_t)B_ * H_ * S_ * D_];   // [bh, s, d]
__device__ float g_O[(size_t)B_ * S_ * H_ * D_];   // [b*s, h*d] row-major

// ---------------------------------------------------------------------------
// Tiled SGEMM: C = A[M,K] @ W[K,N] + bias
// BM=BN=128, BK=16, 256 threads, 8x8 microtile per thread.
// OUT_BHSD=1: scatter output into [b*H+h, s, d] layout (for Q/K/V scratch).
// ---------------------------------------------------------------------------
template <int OUT_BHSD>
__global__ __launch_bounds__(256)
void gemm_bias_kernel(const float* __restrict__ A,
                      const float* __restrict__ W,
                      const float* __restrict__ bias,
                      float* __restrict__ C,
                      int M, int N, int K)
{
    __shared__ float As[16][128];   // [k][m] transposed
    __shared__ float Bs[16][128];   // [k][n]

    const int tid = threadIdx.x;
    const int ty  = tid >> 4;       // 0..15
    const int tx  = tid & 15;       // 0..15
    const int m0  = blockIdx.y * 128;
    const int n0  = blockIdx.x * 128;

    float acc[8][8];
#pragma unroll
    for (int i = 0; i < 8; i++)
#pragma unroll
        for (int j = 0; j < 8; j++) acc[i][j] = 0.0f;

    for (int k0 = 0; k0 < K; k0 += 16) {
        // A tile: 128 rows x 16 cols = 512 float4
#pragma unroll
        for (int it = 0; it < 2; it++) {
            int idx = tid + it * 256;
            int row = idx >> 2;       // 0..127
            int kv  = idx & 3;        // float4 index within 16 cols
            float4 v = *(const float4*)(A + (size_t)(m0 + row) * K + k0 + kv * 4);
            As[kv * 4 + 0][row] = v.x;
            As[kv * 4 + 1][row] = v.y;
            As[kv * 4 + 2][row] = v.z;
            As[kv * 4 + 3][row] = v.w;
        }
        // B tile: 16 rows x 128 cols = 512 float4
#pragma unroll
        for (int it = 0; it < 2; it++) {
            int idx = tid + it * 256;
            int row = idx >> 5;       // 0..15
            int cv  = idx & 31;       // float4 within 128 cols
            *(float4*)(&Bs[row][cv * 4]) =
                *(const float4*)(W + (size_t)(k0 + row) * N + n0 + cv * 4);
        }
        __syncthreads();

#pragma unroll
        for (int k = 0; k < 16; k++) {
            float a[8], b[8];
#pragma unroll
            for (int i = 0; i < 8; i++) a[i] = As[k][ty * 8 + i];
#pragma unroll
            for (int j = 0; j < 8; j++) b[j] = Bs[k][tx * 8 + j];
#pragma unroll
            for (int i = 0; i < 8; i++)
#pragma unroll
                for (int j = 0; j < 8; j++) acc[i][j] = fmaf(a[i], b[j], acc[i][j]);
        }
        __syncthreads();
    }

    // Epilogue
#pragma unroll
    for (int i = 0; i < 8; i++) {
        int m = m0 + ty * 8 + i;
#pragma unroll
        for (int j = 0; j < 8; j++) {
            int n = n0 + tx * 8 + j;
            float v = acc[i][j] + bias[n];
            if (OUT_BHSD) {
                int b = m / S_, s = m - b * S_;
                int h = n >> 6, d = n & 63;
                C[(((size_t)(b * H_ + h)) * S_ + s) * D_ + d] = v;
            } else {
                C[(size_t)m * N + n] = v;
            }
        }
    }
}

// ---------------------------------------------------------------------------
// Flash-style masked attention.
// Grid: (S/64 query tiles, B*H). Block: 256 threads.
// Microtile: rows r_i = ty + i*16, cols c_j = tx + j*16 (lane-stride 1 -> no
// smem bank conflicts with row stride 65).
// ---------------------------------------------------------------------------
#define PSTR 65
#define ATTN_SMEM_BYTES ((4 * 64 * PSTR + 3 * 64) * 4)

__global__ __launch_bounds__(256)
void attn_kernel(const int* __restrict__ mask, float* __restrict__ Og)
{
    extern __shared__ float sm[];
    float* Qs  = sm;                   // 64 x PSTR
    float* Ks  = Qs + 64 * PSTR;
    float* Vs  = Ks + 64 * PSTR;
    float* Ps  = Vs + 64 * PSTR;
    float* m_s = Ps + 64 * PSTR;       // 64
    float* l_s = m_s + 64;             // 64
    float* c_s = l_s + 64;             // 64

    const int tid = threadIdx.x;
    const int ty  = tid >> 4;
    const int tx  = tid & 15;
    const int qbase = blockIdx.x * 64;
    const int bh    = blockIdx.y;

    const float* Qp = g_Q + ((size_t)bh * S_ + qbase) * D_;

    // Load Q tile (coalesced global, stride-65 smem)
#pragma unroll
    for (int it = 0; it < 16; it++) {
        int idx = tid + it * 256;
        int r = idx >> 6, c = idx & 63;
        Qs[r * PSTR + c] = Qp[idx];
    }
    if (tid < 64) { m_s[tid] = -INFINITY; l_s[tid] = 0.0f; }

    float acc[4][4];
#pragma unroll
    for (int i = 0; i < 4; i++)
#pragma unroll
        for (int j = 0; j < 4; j++) acc[i][j] = 0.0f;

    __syncthreads();

    for (int kt = 0; kt < 16; kt++) {
        const int kbase = kt * 64;
        const float* Kp = g_K + ((size_t)bh * S_ + kbase) * D_;
        const float* Vp = g_V + ((size_t)bh * S_ + kbase) * D_;
#pragma unroll
        for (int it = 0; it < 16; it++) {
            int idx = tid + it * 256;
            int r = idx >> 6, c = idx & 63;
            Ks[r * PSTR + c] = Kp[idx];
            Vs[r * PSTR + c] = Vp[idx];
        }
        __syncthreads();

        // GEMM1: S = Q @ K^T  (64x64x64)
        float s[4][4];
#pragma unroll
        for (int i = 0; i < 4; i++)
#pragma unroll
            for (int j = 0; j < 4; j++) s[i][j] = 0.0f;
        for (int d = 0; d < 64; d++) {
            float a[4], b[4];
#pragma unroll
            for (int i = 0; i < 4; i++) a[i] = Qs[(ty + i * 16) * PSTR + d];
#pragma unroll
            for (int j = 0; j < 4; j++) b[j] = Ks[(tx + j * 16) * PSTR + d];
#pragma unroll
            for (int i = 0; i < 4; i++)
#pragma unroll
                for (int j = 0; j < 4; j++) s[i][j] = fmaf(a[i], b[j], s[i][j]);
        }

        // Mask + scale -> Ps
#pragma unroll
        for (int i = 0; i < 4; i++) {
            int qr = ty + i * 16;
            const int* mrow = mask + ((size_t)bh * S_ + (qbase + qr)) * S_ + kbase;
#pragma unroll
            for (int j = 0; j < 4; j++) {
                int c = tx + j * 16;
                float v = (mrow[c] != 0) ? s[i][j] * 0.125f : -INFINITY;
                Ps[qr * PSTR + c] = v;
            }
        }
        __syncthreads();

        // Per-row running max + correction factor
        if (tid < 64) {
            float rm = -INFINITY;
            for (int c = 0; c < 64; c++) rm = fmaxf(rm, Ps[tid * PSTR + c]);
            float mo = m_s[tid];
            float mn = fmaxf(mo, rm);
            c_s[tid] = (mn == -INFINITY) ? 1.0f : __expf(mo - mn);
            m_s[tid] = mn;
        }
        __syncthreads();

        // exp + rescale accumulators
#pragma unroll
        for (int i = 0; i < 4; i++) {
            int qr = ty + i * 16;
            float mn = m_s[qr];
            float cc = c_s[qr];
#pragma unroll
            for (int j = 0; j < 4; j++) {
                int c = tx + j * 16;
                float v = Ps[qr * PSTR + c];
                v = (v == -INFINITY) ? 0.0f : __expf(v - mn);
                Ps[qr * PSTR + c] = v;
                acc[i][j] *= cc;
            }
        }
        __syncthreads();

        // Row sums (runs concurrently with GEMM2; both only read Ps)
        if (tid < 64) {
            float sum = 0.0f;
            for (int c = 0; c < 64; c++) sum += Ps[tid * PSTR + c];
            l_s[tid] = l_s[tid] * c_s[tid] + sum;
        }

        // GEMM2: O += P @ V  (64x64x64)
        for (int k = 0; k < 64; k++) {
            float p[4], vv[4];
#pragma unroll
            for (int i = 0; i < 4; i++) p[i] = Ps[(ty + i * 16) * PSTR + k];
#pragma unroll
            for (int j = 0; j < 4; j++) vv[j] = Vs[k * PSTR + tx + j * 16];
#pragma unroll
            for (int i = 0; i < 4; i++)
#pragma unroll
                for (int j = 0; j < 4; j++) acc[i][j] = fmaf(p[i], vv[j], acc[i][j]);
        }
        __syncthreads();
    }

    // Write to [b*s, h*d] layout for the final GEMM
    const int b = bh >> 4;     // / H_
    const int h = bh & 15;     // % H_
#pragma unroll
    for (int i = 0; i < 4; i++) {
        int qr = ty + i * 16;
        float inv = 1.0f / l_s[qr];
#pragma unroll
        for (int j = 0; j < 4; j++) {
            int c = tx + j * 16;
            Og[((size_t)(b * S_ + qbase + qr)) * (H_ * D_) + h * D_ + c] =
                acc[i][j] * inv;
        }
    }
}

// ---------------------------------------------------------------------------
// Launch
// ---------------------------------------------------------------------------
extern "C" void kernel_launch(void* const* d_in, const int* in_sizes, int n_in,
                              void* d_out, int out_size)
{
    const float* input  = (const float*)d_in[0];
    const float* latent = (const float*)d_in[1];
    const int*   mask   = (const int*)d_in[2];
    const float* Wq = (const float*)d_in[3];
    const float* bq = (const float*)d_in[4];
    const float* Wk = (const float*)d_in[5];
    const float* bk = (const float*)d_in[6];
    const float* Wv = (const float*)d_in[7];
    const float* bv = (const float*)d_in[8];
    const float* Wo = (const float*)d_in[9];
    const float* bo = (const float*)d_in[10];
    float* out = (float*)d_out;

    float *qp, *kp, *vp, *op;
    cudaGetSymbolAddress((void**)&qp, g_Q);
    cudaGetSymbolAddress((void**)&kp, g_K);
    cudaGetSymbolAddress((void**)&vp, g_V);
    cudaGetSymbolAddress((void**)&op, g_O);

    const int M = B_ * S_;        // 8192
    const int N = LAT_;           // 1024
    const int K = LAT_;           // 1024

    dim3 gGemm(N / 128, M / 128); // (8, 64)
    dim3 blk(256);

    // Projections -> [bh, s, d] scratch
    gemm_bias_kernel<1><<<gGemm, blk>>>(latent, Wq, bq, qp, M, N, K);
    gemm_bias_kernel<1><<<gGemm, blk>>>(input,  Wk, bk, kp, M, N, K);
    gemm_bias_kernel<1><<<gGemm, blk>>>(input,  Wv, bv, vp, M, N, K);

    // Attention
    cudaFuncSetAttribute(attn_kernel,
                         cudaFuncAttributeMaxDynamicSharedMemorySize,
                         ATTN_SMEM_BYTES);
    dim3 gAttn(S_ / 64, B_ * H_); // (16, 128)
    attn_kernel<<<gAttn, blk, ATTN_SMEM_BYTES>>>(mask, op);

    // Output projection
    gemm_bias_kernel<0><<<gGemm, blk>>>(op, Wo, bo, out, M, N, K);
}

// round 5
// speedup vs baseline: 2.7801x; 2.7801x over previous
#include <cuda_runtime.h>
#include <math.h>
#include <stdint.h>

// Problem constants
#define B_   8
#define S_   1024
#define H_   16
#define LAT_ 1024
#define D_   64

// ---------------------------------------------------------------------------
// Scratch (__device__ globals: allocation-free rule)
// ---------------------------------------------------------------------------
__device__ float g_Q[(size_t)B_ * H_ * S_ * D_];   // [bh, s, d]
__device__ float g_K[(size_t)B_ * H_ * S_ * D_];   // [bh, s, d]
__device__ float g_V[(size_t)B_ * H_ * S_ * D_];   // [bh, s, d]
__device__ float g_O[(size_t)B_ * S_ * H_ * D_];   // [b*s, h*d]

// ---------------------------------------------------------------------------
// mma.sync m16n8k8 tf32 helpers (compute_80+, no "a"-feature needed)
// Fragment maps (PTX ISA), g = lane>>2, t = lane&3:
//   A(16x8):  a0=(g,t) a1=(g+8,t) a2=(g,t+4) a3=(g+8,t+4)
//   B(8x8):   b0=(t,g) b1=(t+4,g)
//   D(16x8):  d0=(g,2t) d1=(g,2t+1) d2=(g+8,2t) d3=(g+8,2t+1)
// ---------------------------------------------------------------------------
__device__ __forceinline__ void mma_tf32(float* d, const uint32_t* a,
                                         uint32_t b0, uint32_t b1) {
    asm volatile(
        "mma.sync.aligned.m16n8k8.row.col.f32.tf32.tf32.f32 "
        "{%0,%1,%2,%3}, {%4,%5,%6,%7}, {%8,%9}, {%0,%1,%2,%3};"
        : "+f"(d[0]), "+f"(d[1]), "+f"(d[2]), "+f"(d[3])
        : "r"(a[0]), "r"(a[1]), "r"(a[2]), "r"(a[3]), "r"(b0), "r"(b1));
}

__device__ __forceinline__ float to_tf32(float x) {
    uint32_t u;
    asm("cvt.rna.tf32.f32 %0, %1;" : "=r"(u) : "f"(x));
    return __uint_as_float(u);
}

__device__ __forceinline__ uint32_t fbits(float x) { return __float_as_uint(x); }

// ---------------------------------------------------------------------------
// TF32 tensor-core GEMM: C = A[M,1024] @ W[1024,N] + bias
// Tile 128x128, BK=16. 8 warps: warp_m = wid&1 (64 rows), warp_n = wid>>1 (32 cols).
// Smem pads chosen for conflict-free fragment LDS:
//   As[m][k] stride 20  -> bank (20g+t)%32 all-distinct
//   Bs[k][n] stride 136 -> bank (8t+g)    all-distinct
// OUT_BHSD=1: scatter to [b*H+h][s][d] for Q/K/V scratch.
// ---------------------------------------------------------------------------
#define AST 20
#define BST 136

template <int OUT_BHSD>
__global__ __launch_bounds__(256)
void gemm_mma(const float* __restrict__ A, const float* __restrict__ W,
              const float* __restrict__ bias, float* __restrict__ C)
{
    __shared__ float As[128 * AST];
    __shared__ float Bs[16 * BST];

    const int tid  = threadIdx.x;
    const int lane = tid & 31;
    const int wid  = tid >> 5;
    const int g = lane >> 2, t = lane & 3;
    const int wm = (wid & 1) * 64;
    const int wn = (wid >> 1) * 32;
    const int m0 = blockIdx.y * 128;
    const int n0 = blockIdx.x * 128;

    float acc[4][4][4];
#pragma unroll
    for (int i = 0; i < 4; i++)
#pragma unroll
        for (int j = 0; j < 4; j++)
#pragma unroll
            for (int r = 0; r < 4; r++) acc[i][j][r] = 0.0f;

    for (int kt = 0; kt < 64; kt++) {
        const int k0 = kt * 16;
        // Stage A tile [128][16] (natural layout) with tf32 rounding
#pragma unroll
        for (int it = 0; it < 2; it++) {
            int idx = tid + it * 256;          // 0..511 float4
            int row = idx >> 2, c4 = idx & 3;
            float4 v = *(const float4*)(A + (size_t)(m0 + row) * LAT_ + k0 + c4 * 4);
            v.x = to_tf32(v.x); v.y = to_tf32(v.y);
            v.z = to_tf32(v.z); v.w = to_tf32(v.w);
            *(float4*)&As[row * AST + c4 * 4] = v;
        }
        // Stage B tile [16][128] (natural layout)
#pragma unroll
        for (int it = 0; it < 2; it++) {
            int idx = tid + it * 256;
            int row = idx >> 5, cv = idx & 31;
            float4 v = *(const float4*)(W + (size_t)(k0 + row) * LAT_ + n0 + cv * 4);
            v.x = to_tf32(v.x); v.y = to_tf32(v.y);
            v.z = to_tf32(v.z); v.w = to_tf32(v.w);
            *(float4*)&Bs[row * BST + cv * 4] = v;
        }
        __syncthreads();

#pragma unroll
        for (int ks = 0; ks < 2; ks++) {
            uint32_t a[4][4], b[4][2];
#pragma unroll
            for (int i = 0; i < 4; i++) {
                int base = (wm + i * 16 + g) * AST + ks * 8 + t;
                a[i][0] = fbits(As[base]);
                a[i][1] = fbits(As[base + 8 * AST]);
                a[i][2] = fbits(As[base + 4]);
                a[i][3] = fbits(As[base + 8 * AST + 4]);
            }
#pragma unroll
            for (int j = 0; j < 4; j++) {
                int base = (ks * 8 + t) * BST + wn + j * 8 + g;
                b[j][0] = fbits(Bs[base]);
                b[j][1] = fbits(Bs[base + 4 * BST]);
            }
#pragma unroll
            for (int i = 0; i < 4; i++)
#pragma unroll
                for (int j = 0; j < 4; j++)
                    mma_tf32(acc[i][j], a[i], b[j][0], b[j][1]);
        }
        __syncthreads();
    }

    // Epilogue: fragment-direct float2 stores (+bias)
#pragma unroll
    for (int i = 0; i < 4; i++) {
        int r0 = m0 + wm + i * 16 + g;
#pragma unroll
        for (int j = 0; j < 4; j++) {
            int n = n0 + wn + j * 8 + 2 * t;
            float2 bb = *(const float2*)&bias[n];
            float2 v0 = { acc[i][j][0] + bb.x, acc[i][j][1] + bb.y };
            float2 v1 = { acc[i][j][2] + bb.x, acc[i][j][3] + bb.y };
            if (!OUT_BHSD) {
                *(float2*)(C + (size_t)r0 * LAT_ + n)       = v0;
                *(float2*)(C + (size_t)(r0 + 8) * LAT_ + n) = v1;
            } else {
                int bi = r0 >> 10, s = r0 & 1023;
                int h = n >> 6, d = n & 63;
                *(float2*)(C + (((size_t)(bi * H_ + h)) * S_ + s) * D_ + d)     = v0;
                *(float2*)(C + (((size_t)(bi * H_ + h)) * S_ + s + 8) * D_ + d) = v1;
            }
        }
    }
}

// ---------------------------------------------------------------------------
// Tensor-core flash attention. Block: 128 queries, 256 threads (8 warps).
// Warp w owns query rows [w*16, w*16+16) — rows never cross warps, so softmax
// is quad-shfl only and Ps has no cross-warp dependency.
// Smem strides (conflict-free fragment LDS):
//   Ps/Qstage stride 68 (bank 4g+t), Ks stride 68 (bank 4g+t as B of QK^T),
//   Vs stride 72 (bank 8t+g as B of PV).
// ---------------------------------------------------------------------------
#define PST 68
#define KST 68
#define VST 72
#define ATTN_SMEM ((128 * PST + 64 * KST + 64 * VST) * 4)

__global__ __launch_bounds__(256)
void attn_mma_kernel(const int* __restrict__ mask, float* __restrict__ Og)
{
    extern __shared__ float sm[];
    float* Ps = sm;                    // 128 x PST (also Q staging)
    float* Ks = Ps + 128 * PST;        // 64 x KST
    float* Vs = Ks + 64 * KST;         // 64 x VST

    const int tid  = threadIdx.x;
    const int lane = tid & 31;
    const int wid  = tid >> 5;
    const int g = lane >> 2, t = lane & 3;
    const int qbase = blockIdx.x * 128;
    const int bh    = blockIdx.y;
    const int wq    = wid * 16;        // warp's query-row offset in tile

    // Stage Q (tf32) into Ps area
    const float* Qp = g_Q + ((size_t)bh * S_ + qbase) * D_;
#pragma unroll
    for (int it = 0; it < 8; it++) {
        int idx = tid + it * 256;          // 0..2047 float4
        int row = idx >> 4, c4 = idx & 15;
        float4 v = *(const float4*)(Qp + (size_t)row * D_ + c4 * 4);
        v.x = to_tf32(v.x); v.y = to_tf32(v.y);
        v.z = to_tf32(v.z); v.w = to_tf32(v.w);
        *(float4*)&Ps[row * PST + c4 * 4] = v;
    }
    __syncthreads();

    // Q fragments live in registers for the whole kernel: 8 k-steps x 4 regs
    uint32_t qa[8][4];
#pragma unroll
    for (int ks = 0; ks < 8; ks++) {
        int base = (wq + g) * PST + ks * 8 + t;
        qa[ks][0] = fbits(Ps[base]);
        qa[ks][1] = fbits(Ps[base + 8 * PST]);
        qa[ks][2] = fbits(Ps[base + 4]);
        qa[ks][3] = fbits(Ps[base + 8 * PST + 4]);
    }

    float m0r = -INFINITY, m1r = -INFINITY, l0 = 0.0f, l1 = 0.0f;
    float oacc[8][4];
#pragma unroll
    for (int nt = 0; nt < 8; nt++)
#pragma unroll
        for (int r = 0; r < 4; r++) oacc[nt][r] = 0.0f;

    const int* mrow0 = mask + ((size_t)bh * S_ + (qbase + wq + g)) * S_;
    const int* mrow1 = mrow0 + 8 * S_;

    for (int kt = 0; kt < 16; kt++) {
        const int kbase = kt * 64;
        // Stage K, V tiles (64 x 64). Previous iteration's reads finished at
        // the end-of-loop __syncthreads().
        const float* Kp = g_K + ((size_t)bh * S_ + kbase) * D_;
        const float* Vp = g_V + ((size_t)bh * S_ + kbase) * D_;
#pragma unroll
        for (int it = 0; it < 4; it++) {
            int idx = tid + it * 256;          // 0..1023 float4
            int row = idx >> 4, c4 = idx & 15;
            float4 k4 = *(const float4*)(Kp + (size_t)row * D_ + c4 * 4);
            k4.x = to_tf32(k4.x); k4.y = to_tf32(k4.y);
            k4.z = to_tf32(k4.z); k4.w = to_tf32(k4.w);
            *(float4*)&Ks[row * KST + c4 * 4] = k4;
            float4 v4 = *(const float4*)(Vp + (size_t)row * D_ + c4 * 4);
            v4.x = to_tf32(v4.x); v4.y = to_tf32(v4.y);
            v4.z = to_tf32(v4.z); v4.w = to_tf32(v4.w);
            *(float4*)&Vs[row * VST + c4 * 4] = v4;
        }
        __syncthreads();

        // S = Q @ K^T : B[k=d][n=key] = Ks[key][d]
        float sacc[8][4];
#pragma unroll
        for (int nt = 0; nt < 8; nt++)
#pragma unroll
            for (int r = 0; r < 4; r++) sacc[nt][r] = 0.0f;
#pragma unroll
        for (int ks = 0; ks < 8; ks++)
#pragma unroll
            for (int nt = 0; nt < 8; nt++) {
                int base = (nt * 8 + g) * KST + ks * 8 + t;
                mma_tf32(sacc[nt], qa[ks], fbits(Ks[base]), fbits(Ks[base + 4]));
            }

        // Mask + scale (in place), row maxima
        float rm0 = -INFINITY, rm1 = -INFINITY;
#pragma unroll
        for (int nt = 0; nt < 8; nt++) {
            int kc = kbase + nt * 8 + 2 * t;
            int2 mk0 = *(const int2*)&mrow0[kc];
            int2 mk1 = *(const int2*)&mrow1[kc];
            sacc[nt][0] = mk0.x ? sacc[nt][0] * 0.125f : -INFINITY;
            sacc[nt][1] = mk0.y ? sacc[nt][1] * 0.125f : -INFINITY;
            sacc[nt][2] = mk1.x ? sacc[nt][2] * 0.125f : -INFINITY;
            sacc[nt][3] = mk1.y ? sacc[nt][3] * 0.125f : -INFINITY;
            rm0 = fmaxf(rm0, fmaxf(sacc[nt][0], sacc[nt][1]));
            rm1 = fmaxf(rm1, fmaxf(sacc[nt][2], sacc[nt][3]));
        }
        // quad reduction (each row is held by exactly 4 lanes)
#pragma unroll
        for (int off = 1; off <= 2; off <<= 1) {
            rm0 = fmaxf(rm0, __shfl_xor_sync(0xffffffffu, rm0, off));
            rm1 = fmaxf(rm1, __shfl_xor_sync(0xffffffffu, rm1, off));
        }
        float mn0 = fmaxf(m0r, rm0);
        float mn1 = fmaxf(m1r, rm1);
        float corr0 = (mn0 == -INFINITY) ? 1.0f : __expf(m0r - mn0);
        float corr1 = (mn1 == -INFINITY) ? 1.0f : __expf(m1r - mn1);
        m0r = mn0; m1r = mn1;

        // exp, write P (tf32-by-truncation is fine for P), row sums
        float rs0 = 0.0f, rs1 = 0.0f;
#pragma unroll
        for (int nt = 0; nt < 8; nt++) {
            float p0 = (sacc[nt][0] == -INFINITY) ? 0.0f : __expf(sacc[nt][0] - mn0);
            float p1 = (sacc[nt][1] == -INFINITY) ? 0.0f : __expf(sacc[nt][1] - mn0);
            float p2 = (sacc[nt][2] == -INFINITY) ? 0.0f : __expf(sacc[nt][2] - mn1);
            float p3 = (sacc[nt][3] == -INFINITY) ? 0.0f : __expf(sacc[nt][3] - mn1);
            rs0 += p0 + p1;  rs1 += p2 + p3;
            float2 w0 = { p0, p1 }, w1 = { p2, p3 };
            *(float2*)&Ps[(wq + g) * PST + nt * 8 + 2 * t]     = w0;
            *(float2*)&Ps[(wq + g + 8) * PST + nt * 8 + 2 * t] = w1;
        }
#pragma unroll
        for (int off = 1; off <= 2; off <<= 1) {
            rs0 += __shfl_xor_sync(0xffffffffu, rs0, off);
            rs1 += __shfl_xor_sync(0xffffffffu, rs1, off);
        }
        l0 = l0 * corr0 + rs0;
        l1 = l1 * corr1 + rs1;
#pragma unroll
        for (int nt = 0; nt < 8; nt++) {
            oacc[nt][0] *= corr0; oacc[nt][1] *= corr0;
            oacc[nt][2] *= corr1; oacc[nt][3] *= corr1;
        }
        __syncwarp();   // Ps rows are warp-private; order STS -> LDS in-warp

        // O += P @ V : A[q][key] = Ps, B[k=key][n=d] = Vs[key][d]
#pragma unroll
        for (int ks = 0; ks < 8; ks++) {
            uint32_t pa[4];
            int base = (wq + g) * PST + ks * 8 + t;
            pa[0] = fbits(Ps[base]);
            pa[1] = fbits(Ps[base + 8 * PST]);
            pa[2] = fbits(Ps[base + 4]);
            pa[3] = fbits(Ps[base + 8 * PST + 4]);
#pragma unroll
            for (int nt = 0; nt < 8; nt++) {
                int vb = (ks * 8 + t) * VST + nt * 8 + g;
                mma_tf32(oacc[nt], pa, fbits(Vs[vb]), fbits(Vs[vb + 4 * VST]));
            }
        }
        __syncthreads();   // all reads of Ks/Vs done before next staging
    }

    // Final normalize + write [b*s][h*64+d]
    const int b = bh >> 4;
    const int h = bh & 15;
    const int r0 = qbase + wq + g;
    float inv0 = 1.0f / l0, inv1 = 1.0f / l1;
#pragma unroll
    for (int nt = 0; nt < 8; nt++) {
        int col = h * D_ + nt * 8 + 2 * t;
        float2 v0 = { oacc[nt][0] * inv0, oacc[nt][1] * inv0 };
        float2 v1 = { oacc[nt][2] * inv1, oacc[nt][3] * inv1 };
        *(float2*)(Og + ((size_t)(b * S_ + r0)) * (H_ * D_) + col)     = v0;
        *(float2*)(Og + ((size_t)(b * S_ + r0 + 8)) * (H_ * D_) + col) = v1;
    }
}

// ---------------------------------------------------------------------------
// Launch
// ---------------------------------------------------------------------------
extern "C" void kernel_launch(void* const* d_in, const int* in_sizes, int n_in,
                              void* d_out, int out_size)
{
    const float* input  = (const float*)d_in[0];
    const float* latent = (const float*)d_in[1];
    const int*   mask   = (const int*)d_in[2];
    const float* Wq = (const float*)d_in[3];
    const float* bq = (const float*)d_in[4];
    const float* Wk = (const float*)d_in[5];
    const float* bk = (const float*)d_in[6];
    const float* Wv = (const float*)d_in[7];
    const float* bv = (const float*)d_in[8];
    const float* Wo = (const float*)d_in[9];
    const float* bo = (const float*)d_in[10];
    float* out = (float*)d_out;

    float *qp, *kp, *vp, *op;
    cudaGetSymbolAddress((void**)&qp, g_Q);
    cudaGetSymbolAddress((void**)&kp, g_K);
    cudaGetSymbolAddress((void**)&vp, g_V);
    cudaGetSymbolAddress((void**)&op, g_O);

    cudaFuncSetAttribute(attn_mma_kernel,
                         cudaFuncAttributeMaxDynamicSharedMemorySize, ATTN_SMEM);

    dim3 gg(LAT_ / 128, (B_ * S_) / 128);   // (8, 64)
    gemm_mma<1><<<gg, 256>>>(latent, Wq, bq, qp);
    gemm_mma<1><<<gg, 256>>>(input,  Wk, bk, kp);
    gemm_mma<1><<<gg, 256>>>(input,  Wv, bv, vp);

    dim3 ga(S_ / 128, B_ * H_);             // (8, 128)
    attn_mma_kernel<<<ga, 256, ATTN_SMEM>>>(mask, op);

    gemm_mma<0><<<gg, 256>>>(op, Wo, bo, out);
}

// round 6
// speedup vs baseline: 2.9827x; 1.0729x over previous
#include <cuda_runtime.h>
#include <math.h>
#include <stdint.h>

// Problem constants
#define B_   8
#define S_   1024
#define H_   16
#define LAT_ 1024
#define D_   64

// ---------------------------------------------------------------------------
// Scratch (__device__ globals: allocation-free rule)
// ---------------------------------------------------------------------------
__device__ float g_Q[(size_t)B_ * H_ * S_ * D_];   // [bh, s, d]
__device__ float g_K[(size_t)B_ * H_ * S_ * D_];   // [bh, s, d]
__device__ float g_V[(size_t)B_ * H_ * S_ * D_];   // [bh, s, d]
__device__ float g_O[(size_t)B_ * S_ * H_ * D_];   // [b*s, h*d]

// ---------------------------------------------------------------------------
// mma.sync m16n8k8 tf32 helpers (compute_80+)
// Fragment maps (PTX ISA), g = lane>>2, t = lane&3:
//   A(16x8):  a0=(g,t) a1=(g+8,t) a2=(g,t+4) a3=(g+8,t+4)
//   B(8x8):   b0=(t,g) b1=(t+4,g)
//   D(16x8):  d0=(g,2t) d1=(g,2t+1) d2=(g+8,2t) d3=(g+8,2t+1)
// ---------------------------------------------------------------------------
__device__ __forceinline__ void mma_tf32(float* d, const uint32_t* a,
                                         uint32_t b0, uint32_t b1) {
    asm volatile(
        "mma.sync.aligned.m16n8k8.row.col.f32.tf32.tf32.f32 "
        "{%0,%1,%2,%3}, {%4,%5,%6,%7}, {%8,%9}, {%0,%1,%2,%3};"
        : "+f"(d[0]), "+f"(d[1]), "+f"(d[2]), "+f"(d[3])
        : "r"(a[0]), "r"(a[1]), "r"(a[2]), "r"(a[3]), "r"(b0), "r"(b1));
}

__device__ __forceinline__ float to_tf32(float x) {
    uint32_t u;
    asm("cvt.rna.tf32.f32 %0, %1;" : "=r"(u) : "f"(x));
    return __uint_as_float(u);
}

__device__ __forceinline__ float4 to_tf32_4(float4 v) {
    v.x = to_tf32(v.x); v.y = to_tf32(v.y);
    v.z = to_tf32(v.z); v.w = to_tf32(v.w);
    return v;
}

__device__ __forceinline__ uint32_t fbits(float x) { return __float_as_uint(x); }

// ---------------------------------------------------------------------------
// TF32 tensor-core GEMM: C = A[M,1024] @ W[1024,N] + bias
// Tile 128x128, BK=16, register-staged double pipeline.
// 8 warps: warp_m = wid&1 (64 rows), warp_n = wid>>1 (32 cols).
// Smem pads for conflict-free fragment LDS:
//   As[m][k] stride 20  -> bank (20g+t)%32 all-distinct
//   Bs[k][n] stride 136 -> bank (8t+g)    all-distinct
// OUT_BHSD=1: scatter to [b*H+h][s][d] for Q/K/V scratch.
// ---------------------------------------------------------------------------
#define AST 20
#define BST 136

template <int OUT_BHSD>
__global__ __launch_bounds__(256)
void gemm_mma(const float* __restrict__ A, const float* __restrict__ W,
              const float* __restrict__ bias, float* __restrict__ C)
{
    __shared__ float As[128 * AST];
    __shared__ float Bs[16 * BST];

    const int tid  = threadIdx.x;
    const int lane = tid & 31;
    const int wid  = tid >> 5;
    const int g = lane >> 2, t = lane & 3;
    const int wm = (wid & 1) * 64;
    const int wn = (wid >> 1) * 32;
    const int m0 = blockIdx.y * 128;
    const int n0 = blockIdx.x * 128;

    // Per-thread staging addresses (fixed across kt, advance by 16 in k)
    const int aidx0 = tid,        aidx1 = tid + 256;    // A: 512 float4/tile
    const int arow0 = aidx0 >> 2, ac0 = (aidx0 & 3) * 4;
    const int arow1 = aidx1 >> 2, ac1 = (aidx1 & 3) * 4;
    const int brow0 = aidx0 >> 5, bc0 = (aidx0 & 31) * 4;
    const int brow1 = aidx1 >> 5, bc1 = (aidx1 & 31) * 4;
    const float* gA0 = A + (size_t)(m0 + arow0) * LAT_ + ac0;
    const float* gA1 = A + (size_t)(m0 + arow1) * LAT_ + ac1;
    const float* gB0 = W + (size_t)brow0 * LAT_ + n0 + bc0;
    const float* gB1 = W + (size_t)brow1 * LAT_ + n0 + bc1;

    float acc[4][4][4];
#pragma unroll
    for (int i = 0; i < 4; i++)
#pragma unroll
        for (int j = 0; j < 4; j++)
#pragma unroll
            for (int r = 0; r < 4; r++) acc[i][j][r] = 0.0f;

    // Prologue: stage kt=0
    float4 ra0 = *(const float4*)(gA0);
    float4 ra1 = *(const float4*)(gA1);
    float4 rb0 = *(const float4*)(gB0);
    float4 rb1 = *(const float4*)(gB1);
    *(float4*)&As[arow0 * AST + ac0] = to_tf32_4(ra0);
    *(float4*)&As[arow1 * AST + ac1] = to_tf32_4(ra1);
    *(float4*)&Bs[brow0 * BST + bc0] = to_tf32_4(rb0);
    *(float4*)&Bs[brow1 * BST + bc1] = to_tf32_4(rb1);
    __syncthreads();

    for (int kt = 0; kt < 64; kt++) {
        // Issue next tile's global loads (consumed after the MMA phase)
        if (kt < 63) {
            const int ko = (kt + 1) * 16;
            ra0 = *(const float4*)(gA0 + ko);
            ra1 = *(const float4*)(gA1 + ko);
            rb0 = *(const float4*)(gB0 + (size_t)ko * LAT_);
            rb1 = *(const float4*)(gB1 + (size_t)ko * LAT_);
        }

#pragma unroll
        for (int ks = 0; ks < 2; ks++) {
            uint32_t a[4][4], b[4][2];
#pragma unroll
            for (int i = 0; i < 4; i++) {
                int base = (wm + i * 16 + g) * AST + ks * 8 + t;
                a[i][0] = fbits(As[base]);
                a[i][1] = fbits(As[base + 8 * AST]);
                a[i][2] = fbits(As[base + 4]);
                a[i][3] = fbits(As[base + 8 * AST + 4]);
            }
#pragma unroll
            for (int j = 0; j < 4; j++) {
                int base = (ks * 8 + t) * BST + wn + j * 8 + g;
                b[j][0] = fbits(Bs[base]);
                b[j][1] = fbits(Bs[base + 4 * BST]);
            }
#pragma unroll
            for (int i = 0; i < 4; i++)
#pragma unroll
                for (int j = 0; j < 4; j++)
                    mma_tf32(acc[i][j], a[i], b[j][0], b[j][1]);
        }
        __syncthreads();
        if (kt < 63) {
            *(float4*)&As[arow0 * AST + ac0] = to_tf32_4(ra0);
            *(float4*)&As[arow1 * AST + ac1] = to_tf32_4(ra1);
            *(float4*)&Bs[brow0 * BST + bc0] = to_tf32_4(rb0);
            *(float4*)&Bs[brow1 * BST + bc1] = to_tf32_4(rb1);
            __syncthreads();
        }
    }

    // Epilogue: fragment-direct float2 stores (+bias)
#pragma unroll
    for (int i = 0; i < 4; i++) {
        int r0 = m0 + wm + i * 16 + g;
#pragma unroll
        for (int j = 0; j < 4; j++) {
            int n = n0 + wn + j * 8 + 2 * t;
            float2 bb = *(const float2*)&bias[n];
            float2 v0 = { acc[i][j][0] + bb.x, acc[i][j][1] + bb.y };
            float2 v1 = { acc[i][j][2] + bb.x, acc[i][j][3] + bb.y };
            if (!OUT_BHSD) {
                *(float2*)(C + (size_t)r0 * LAT_ + n)       = v0;
                *(float2*)(C + (size_t)(r0 + 8) * LAT_ + n) = v1;
            } else {
                int bi = r0 >> 10, s = r0 & 1023;
                int h = n >> 6, d = n & 63;
                *(float2*)(C + (((size_t)(bi * H_ + h)) * S_ + s) * D_ + d)     = v0;
                *(float2*)(C + (((size_t)(bi * H_ + h)) * S_ + s + 8) * D_ + d) = v1;
            }
        }
    }
}

// ---------------------------------------------------------------------------
// Tensor-core flash attention, register-pipelined.
// Block: 128 queries, 256 threads (8 warps). Warp w owns query rows
// [w*16, w*16+16) — softmax is quad-shfl only; Ps rows are warp-private.
// Smem strides (conflict-free fragment LDS):
//   Ps/Qstage stride 68 (bank 4g+t), Ks stride 68, Vs stride 72 (bank 8t+g).
// Pipelining: K/V tile for kt+1 prefetched into registers before the MMA
// phases of kt; mask for kt prefetched before the QK MMAs.
// exp2-domain softmax: scores scaled by 0.125*log2(e), exp2f = bare MUFU.
// ---------------------------------------------------------------------------
#define PST 68
#define KST 68
#define VST 72
#define ATTN_SMEM ((128 * PST + 64 * KST + 64 * VST) * 4)
#define SCL 0.1803368801111244f   /* 0.125 * log2(e) */

__global__ __launch_bounds__(256)
void attn_mma_kernel(const int* __restrict__ mask, float* __restrict__ Og)
{
    extern __shared__ float sm[];
    float* Ps = sm;                    // 128 x PST (also Q staging)
    float* Ks = Ps + 128 * PST;        // 64 x KST
    float* Vs = Ks + 64 * KST;         // 64 x VST

    const int tid  = threadIdx.x;
    const int lane = tid & 31;
    const int wid  = tid >> 5;
    const int g = lane >> 2, t = lane & 3;
    const int qbase = blockIdx.x * 128;
    const int bh    = blockIdx.y;
    const int wq    = wid * 16;

    // K/V staging map: 4 rows per thread per tile (1024 float4 / 256 threads)
    const int srow0 = tid >> 4;          // 0..15  (+16*it)
    const int sc4   = (tid & 15) * 4;
    const float* Kbase = g_K + ((size_t)bh * S_) * D_ + (size_t)srow0 * D_ + sc4;
    const float* Vbase = g_V + ((size_t)bh * S_) * D_ + (size_t)srow0 * D_ + sc4;

    // Stage Q (tf32) into Ps area; stage K/V tile 0 (direct, prologue)
    const float* Qp = g_Q + ((size_t)bh * S_ + qbase) * D_;
#pragma unroll
    for (int it = 0; it < 8; it++) {
        int idx = tid + it * 256;
        int row = idx >> 4, c4 = (idx & 15) * 4;
        *(float4*)&Ps[row * PST + c4] =
            to_tf32_4(*(const float4*)(Qp + (size_t)row * D_ + c4));
    }
#pragma unroll
    for (int it = 0; it < 4; it++) {
        int row = srow0 + it * 16;
        *(float4*)&Ks[row * KST + sc4] =
            to_tf32_4(*(const float4*)(Kbase + (size_t)(it * 16) * D_));
        *(float4*)&Vs[row * VST + sc4] =
            to_tf32_4(*(const float4*)(Vbase + (size_t)(it * 16) * D_));
    }
    __syncthreads();

    // Q fragments in registers for the whole kernel
    uint32_t qa[8][4];
#pragma unroll
    for (int ks = 0; ks < 8; ks++) {
        int base = (wq + g) * PST + ks * 8 + t;
        qa[ks][0] = fbits(Ps[base]);
        qa[ks][1] = fbits(Ps[base + 8 * PST]);
        qa[ks][2] = fbits(Ps[base + 4]);
        qa[ks][3] = fbits(Ps[base + 8 * PST + 4]);
    }

    float m0r = -INFINITY, m1r = -INFINITY, l0 = 0.0f, l1 = 0.0f;
    float oacc[8][4];
#pragma unroll
    for (int nt = 0; nt < 8; nt++)
#pragma unroll
        for (int r = 0; r < 4; r++) oacc[nt][r] = 0.0f;

    const int* mrow0 = mask + ((size_t)bh * S_ + (qbase + wq + g)) * S_;
    const int* mrow1 = mrow0 + 8 * S_;

    float4 kst[4], vst[4];   // next-tile staging registers

    for (int kt = 0; kt < 16; kt++) {
        const int kbase = kt * 64;

        // Prefetch mask for THIS tile (used after 64 QK MMAs — latency hidden)
        int2 mk0[8], mk1[8];
#pragma unroll
        for (int nt = 0; nt < 8; nt++) {
            mk0[nt] = *(const int2*)&mrow0[kbase + nt * 8 + 2 * t];
            mk1[nt] = *(const int2*)&mrow1[kbase + nt * 8 + 2 * t];
        }
        // Prefetch K/V for NEXT tile (consumed by STS after PV MMAs)
        if (kt < 15) {
            const size_t off = (size_t)(kbase + 64) * D_;
#pragma unroll
            for (int it = 0; it < 4; it++) {
                kst[it] = *(const float4*)(Kbase + off + (size_t)(it * 16) * D_);
                vst[it] = *(const float4*)(Vbase + off + (size_t)(it * 16) * D_);
            }
        }

        // S = Q @ K^T : B[k=d][n=key] = Ks[key][d]
        float sacc[8][4];
#pragma unroll
        for (int nt = 0; nt < 8; nt++)
#pragma unroll
            for (int r = 0; r < 4; r++) sacc[nt][r] = 0.0f;
#pragma unroll
        for (int ks = 0; ks < 8; ks++)
#pragma unroll
            for (int nt = 0; nt < 8; nt++) {
                int base = (nt * 8 + g) * KST + ks * 8 + t;
                mma_tf32(sacc[nt], qa[ks], fbits(Ks[base]), fbits(Ks[base + 4]));
            }

        // Mask + exp2-domain scale, row maxima
        float rm0 = -INFINITY, rm1 = -INFINITY;
#pragma unroll
        for (int nt = 0; nt < 8; nt++) {
            sacc[nt][0] = mk0[nt].x ? sacc[nt][0] * SCL : -INFINITY;
            sacc[nt][1] = mk0[nt].y ? sacc[nt][1] * SCL : -INFINITY;
            sacc[nt][2] = mk1[nt].x ? sacc[nt][2] * SCL : -INFINITY;
            sacc[nt][3] = mk1[nt].y ? sacc[nt][3] * SCL : -INFINITY;
            rm0 = fmaxf(rm0, fmaxf(sacc[nt][0], sacc[nt][1]));
            rm1 = fmaxf(rm1, fmaxf(sacc[nt][2], sacc[nt][3]));
        }
#pragma unroll
        for (int off = 1; off <= 2; off <<= 1) {
            rm0 = fmaxf(rm0, __shfl_xor_sync(0xffffffffu, rm0, off));
            rm1 = fmaxf(rm1, __shfl_xor_sync(0xffffffffu, rm1, off));
        }
        float mn0 = fmaxf(m0r, rm0);
        float mn1 = fmaxf(m1r, rm1);
        float corr0 = (mn0 == -INFINITY) ? 1.0f : exp2f(m0r - mn0);
        float corr1 = (mn1 == -INFINITY) ? 1.0f : exp2f(m1r - mn1);
        m0r = mn0; m1r = mn1;

        // exp2, write P, row sums
        float rs0 = 0.0f, rs1 = 0.0f;
#pragma unroll
        for (int nt = 0; nt < 8; nt++) {
            float p0 = (sacc[nt][0] == -INFINITY) ? 0.0f : exp2f(sacc[nt][0] - mn0);
            float p1 = (sacc[nt][1] == -INFINITY) ? 0.0f : exp2f(sacc[nt][1] - mn0);
            float p2 = (sacc[nt][2] == -INFINITY) ? 0.0f : exp2f(sacc[nt][2] - mn1);
            float p3 = (sacc[nt][3] == -INFINITY) ? 0.0f : exp2f(sacc[nt][3] - mn1);
            rs0 += p0 + p1;  rs1 += p2 + p3;
            float2 w0 = { p0, p1 }, w1 = { p2, p3 };
            *(float2*)&Ps[(wq + g) * PST + nt * 8 + 2 * t]     = w0;
            *(float2*)&Ps[(wq + g + 8) * PST + nt * 8 + 2 * t] = w1;
        }
#pragma unroll
        for (int off = 1; off <= 2; off <<= 1) {
            rs0 += __shfl_xor_sync(0xffffffffu, rs0, off);
            rs1 += __shfl_xor_sync(0xffffffffu, rs1, off);
        }
        l0 = l0 * corr0 + rs0;
        l1 = l1 * corr1 + rs1;
#pragma unroll
        for (int nt = 0; nt < 8; nt++) {
            oacc[nt][0] *= corr0; oacc[nt][1] *= corr0;
            oacc[nt][2] *= corr1; oacc[nt][3] *= corr1;
        }
        __syncwarp();   // order P STS -> LDS within the warp

        // O += P @ V : A = Ps rows (warp-private), B[k=key][n=d] = Vs[key][d]
#pragma unroll
        for (int ks = 0; ks < 8; ks++) {
            uint32_t pa[4];
            int base = (wq + g) * PST + ks * 8 + t;
            pa[0] = fbits(Ps[base]);
            pa[1] = fbits(Ps[base + 8 * PST]);
            pa[2] = fbits(Ps[base + 4]);
            pa[3] = fbits(Ps[base + 8 * PST + 4]);
#pragma unroll
            for (int nt = 0; nt < 8; nt++) {
                int vb = (ks * 8 + t) * VST + nt * 8 + g;
                mma_tf32(oacc[nt], pa, fbits(Vs[vb]), fbits(Vs[vb + 4 * VST]));
            }
        }
        __syncthreads();   // all reads of Ks/Vs done
        if (kt < 15) {     // store prefetched next tile
#pragma unroll
            for (int it = 0; it < 4; it++) {
                int row = srow0 + it * 16;
                *(float4*)&Ks[row * KST + sc4] = to_tf32_4(kst[it]);
                *(float4*)&Vs[row * VST + sc4] = to_tf32_4(vst[it]);
            }
            __syncthreads();
        }
    }

    // Final normalize + write [b*s][h*64+d]
    const int b = bh >> 4;
    const int h = bh & 15;
    const int r0 = qbase + wq + g;
    float inv0 = 1.0f / l0, inv1 = 1.0f / l1;
#pragma unroll
    for (int nt = 0; nt < 8; nt++) {
        int col = h * D_ + nt * 8 + 2 * t;
        float2 v0 = { oacc[nt][0] * inv0, oacc[nt][1] * inv0 };
        float2 v1 = { oacc[nt][2] * inv1, oacc[nt][3] * inv1 };
        *(float2*)(Og + ((size_t)(b * S_ + r0)) * (H_ * D_) + col)     = v0;
        *(float2*)(Og + ((size_t)(b * S_ + r0 + 8)) * (H_ * D_) + col) = v1;
    }
}

// ---------------------------------------------------------------------------
// Launch
// ---------------------------------------------------------------------------
extern "C" void kernel_launch(void* const* d_in, const int* in_sizes, int n_in,
                              void* d_out, int out_size)
{
    const float* input  = (const float*)d_in[0];
    const float* latent = (const float*)d_in[1];
    const int*   mask   = (const int*)d_in[2];
    const float* Wq = (const float*)d_in[3];
    const float* bq = (const float*)d_in[4];
    const float* Wk = (const float*)d_in[5];
    const float* bk = (const float*)d_in[6];
    const float* Wv = (const float*)d_in[7];
    const float* bv = (const float*)d_in[8];
    const float* Wo = (const float*)d_in[9];
    const float* bo = (const float*)d_in[10];
    float* out = (float*)d_out;

    float *qp, *kp, *vp, *op;
    cudaGetSymbolAddress((void**)&qp, g_Q);
    cudaGetSymbolAddress((void**)&kp, g_K);
    cudaGetSymbolAddress((void**)&vp, g_V);
    cudaGetSymbolAddress((void**)&op, g_O);

    cudaFuncSetAttribute(attn_mma_kernel,
                         cudaFuncAttributeMaxDynamicSharedMemorySize, ATTN_SMEM);

    dim3 gg(LAT_ / 128, (B_ * S_) / 128);   // (8, 64)
    gemm_mma<1><<<gg, 256>>>(latent, Wq, bq, qp);
    gemm_mma<1><<<gg, 256>>>(input,  Wk, bk, kp);
    gemm_mma<1><<<gg, 256>>>(input,  Wv, bv, vp);

    dim3 ga(S_ / 128, B_ * H_);             // (8, 128)
    attn_mma_kernel<<<ga, 256, ATTN_SMEM>>>(mask, op);

    gemm_mma<0><<<gg, 256>>>(op, Wo, bo, out);
}

// round 7
// speedup vs baseline: 3.0873x; 1.0351x over previous
#include <cuda_runtime.h>
#include <math.h>
#include <stdint.h>

// Problem constants
#define B_   8
#define S_   1024
#define H_   16
#define LAT_ 1024
#define D_   64

// ---------------------------------------------------------------------------
// Scratch (__device__ globals: allocation-free rule)
// ---------------------------------------------------------------------------
__device__ float g_Q[(size_t)B_ * H_ * S_ * D_];   // [bh, s, d]
__device__ float g_K[(size_t)B_ * H_ * S_ * D_];   // [bh, s, d]
__device__ float g_V[(size_t)B_ * H_ * S_ * D_];   // [bh, s, d]
__device__ float g_O[(size_t)B_ * S_ * H_ * D_];   // [b*s, h*d]

// ---------------------------------------------------------------------------
// mma.sync m16n8k8 tf32 helpers (compute_80+)
// Fragment maps (PTX ISA), g = lane>>2, t = lane&3:
//   A(16x8):  a0=(g,t) a1=(g+8,t) a2=(g,t+4) a3=(g+8,t+4)
//   B(8x8):   b0=(t,g) b1=(t+4,g)
//   D(16x8):  d0=(g,2t) d1=(g,2t+1) d2=(g+8,2t) d3=(g+8,2t+1)
// ---------------------------------------------------------------------------
__device__ __forceinline__ void mma_tf32(float* d, const uint32_t* a,
                                         uint32_t b0, uint32_t b1) {
    asm volatile(
        "mma.sync.aligned.m16n8k8.row.col.f32.tf32.tf32.f32 "
        "{%0,%1,%2,%3}, {%4,%5,%6,%7}, {%8,%9}, {%0,%1,%2,%3};"
        : "+f"(d[0]), "+f"(d[1]), "+f"(d[2]), "+f"(d[3])
        : "r"(a[0]), "r"(a[1]), "r"(a[2]), "r"(a[3]), "r"(b0), "r"(b1));
}

__device__ __forceinline__ float to_tf32(float x) {
    uint32_t u;
    asm("cvt.rna.tf32.f32 %0, %1;" : "=r"(u) : "f"(x));
    return __uint_as_float(u);
}

__device__ __forceinline__ float4 to_tf32_4(float4 v) {
    v.x = to_tf32(v.x); v.y = to_tf32(v.y);
    v.z = to_tf32(v.z); v.w = to_tf32(v.w);
    return v;
}

__device__ __forceinline__ uint32_t fbits(float x) { return __float_as_uint(x); }

// ---------------------------------------------------------------------------
// TF32 tensor-core GEMM: C = A[M,1024] @ W[1024,N] + bias
// Tile 128x128, BK=16, register-staged pipeline, 2 CTAs/SM (regs capped 128).
// 8 warps: warp_m = wid&1 (64 rows), warp_n = wid>>1 (32 cols).
// As stride 20, Bs stride 136: conflict-free fragment LDS (verified).
// OUT_BHSD=1: scatter to [b*H+h][s][d] for Q/K/V scratch.
// ---------------------------------------------------------------------------
#define AST 20
#define BST 136

template <int OUT_BHSD>
__global__ __launch_bounds__(256, 2)
void gemm_mma(const float* __restrict__ A, const float* __restrict__ W,
              const float* __restrict__ bias, float* __restrict__ C)
{
    __shared__ float As[128 * AST];
    __shared__ float Bs[16 * BST];

    const int tid  = threadIdx.x;
    const int lane = tid & 31;
    const int wid  = tid >> 5;
    const int g = lane >> 2, t = lane & 3;
    const int wm = (wid & 1) * 64;
    const int wn = (wid >> 1) * 32;
    const int m0 = blockIdx.y * 128;
    const int n0 = blockIdx.x * 128;

    const int aidx0 = tid,        aidx1 = tid + 256;
    const int arow0 = aidx0 >> 2, ac0 = (aidx0 & 3) * 4;
    const int arow1 = aidx1 >> 2, ac1 = (aidx1 & 3) * 4;
    const int brow0 = aidx0 >> 5, bc0 = (aidx0 & 31) * 4;
    const int brow1 = aidx1 >> 5, bc1 = (aidx1 & 31) * 4;
    const float* gA0 = A + (size_t)(m0 + arow0) * LAT_ + ac0;
    const float* gA1 = A + (size_t)(m0 + arow1) * LAT_ + ac1;
    const float* gB0 = W + (size_t)brow0 * LAT_ + n0 + bc0;
    const float* gB1 = W + (size_t)brow1 * LAT_ + n0 + bc1;

    float acc[4][4][4];
#pragma unroll
    for (int i = 0; i < 4; i++)
#pragma unroll
        for (int j = 0; j < 4; j++)
#pragma unroll
            for (int r = 0; r < 4; r++) acc[i][j][r] = 0.0f;

    // Prologue: stage kt=0
    {
        float4 ra0 = *(const float4*)(gA0);
        float4 ra1 = *(const float4*)(gA1);
        float4 rb0 = *(const float4*)(gB0);
        float4 rb1 = *(const float4*)(gB1);
        *(float4*)&As[arow0 * AST + ac0] = to_tf32_4(ra0);
        *(float4*)&As[arow1 * AST + ac1] = to_tf32_4(ra1);
        *(float4*)&Bs[brow0 * BST + bc0] = to_tf32_4(rb0);
        *(float4*)&Bs[brow1 * BST + bc1] = to_tf32_4(rb1);
    }
    __syncthreads();

    for (int kt = 0; kt < 64; kt++) {
        float4 ra0, ra1, rb0, rb1;
        if (kt < 63) {
            const int ko = (kt + 1) * 16;
            ra0 = *(const float4*)(gA0 + ko);
            ra1 = *(const float4*)(gA1 + ko);
            rb0 = *(const float4*)(gB0 + (size_t)ko * LAT_);
            rb1 = *(const float4*)(gB1 + (size_t)ko * LAT_);
        }

#pragma unroll
        for (int ks = 0; ks < 2; ks++) {
            uint32_t a[4][4], b[4][2];
#pragma unroll
            for (int i = 0; i < 4; i++) {
                int base = (wm + i * 16 + g) * AST + ks * 8 + t;
                a[i][0] = fbits(As[base]);
                a[i][1] = fbits(As[base + 8 * AST]);
                a[i][2] = fbits(As[base + 4]);
                a[i][3] = fbits(As[base + 8 * AST + 4]);
            }
#pragma unroll
            for (int j = 0; j < 4; j++) {
                int base = (ks * 8 + t) * BST + wn + j * 8 + g;
                b[j][0] = fbits(Bs[base]);
                b[j][1] = fbits(Bs[base + 4 * BST]);
            }
#pragma unroll
            for (int i = 0; i < 4; i++)
#pragma unroll
                for (int j = 0; j < 4; j++)
                    mma_tf32(acc[i][j], a[i], b[j][0], b[j][1]);
        }
        __syncthreads();
        if (kt < 63) {
            *(float4*)&As[arow0 * AST + ac0] = to_tf32_4(ra0);
            *(float4*)&As[arow1 * AST + ac1] = to_tf32_4(ra1);
            *(float4*)&Bs[brow0 * BST + bc0] = to_tf32_4(rb0);
            *(float4*)&Bs[brow1 * BST + bc1] = to_tf32_4(rb1);
            __syncthreads();
        }
    }

#pragma unroll
    for (int i = 0; i < 4; i++) {
        int r0 = m0 + wm + i * 16 + g;
#pragma unroll
        for (int j = 0; j < 4; j++) {
            int n = n0 + wn + j * 8 + 2 * t;
            float2 bb = *(const float2*)&bias[n];
            float2 v0 = { acc[i][j][0] + bb.x, acc[i][j][1] + bb.y };
            float2 v1 = { acc[i][j][2] + bb.x, acc[i][j][3] + bb.y };
            if (!OUT_BHSD) {
                *(float2*)(C + (size_t)r0 * LAT_ + n)       = v0;
                *(float2*)(C + (size_t)(r0 + 8) * LAT_ + n) = v1;
            } else {
                int bi = r0 >> 10, s = r0 & 1023;
                int h = n >> 6, d = n & 63;
                *(float2*)(C + (((size_t)(bi * H_ + h)) * S_ + s) * D_ + d)     = v0;
                *(float2*)(C + (((size_t)(bi * H_ + h)) * S_ + s + 8) * D_ + d) = v1;
            }
        }
    }
}

// ---------------------------------------------------------------------------
// Tensor-core flash attention, fragment-major smem, 2 CTAs/SM.
// Block: 128 queries, 256 threads (8 warps); warp w owns rows [16w,16w+16).
// Smem (per CTA, 100352 B):
//   Qf [wid][ks][lane] float4  A-frags of Q      (32 KB)  -> LDS.128
//   Pf [wid][ks][lane] float4  A-frags of P      (32 KB)  -> LDS.128
//   Kf [nt*8+ks][lane] float2  B-frags of QK^T   (17408)  -> LDS.64
//   Vf [ks*8+nt][lane] float2  B-frags of PV     (17408)  -> LDS.64
// Kf/Vf chunk stride 68 floats (=272B) removes staging-store conflicts.
// exp2-domain softmax (scores pre-scaled by 0.125*log2 e).
// ---------------------------------------------------------------------------
#define QF_OFF 0
#define PF_OFF 32768
#define KF_OFF 65536
#define VF_OFF (65536 + 17408)
#define ATTN_SMEM (65536 + 2 * 17408)
#define SCL 0.1803368801111244f   /* 0.125 * log2(e) */

__global__ __launch_bounds__(256, 2)
void attn_mma_kernel(const int* __restrict__ mask, float* __restrict__ Og)
{
    extern __shared__ __align__(16) char smem[];
    float* Qf   = (float*)(smem + QF_OFF);
    float* Pf   = (float*)(smem + PF_OFF);
    float* Kf   = (float*)(smem + KF_OFF);
    float* Vf   = (float*)(smem + VF_OFF);
    float* Qtmp = (float*)(smem + KF_OFF);   // transient: 128 x 68 floats

    const int tid  = threadIdx.x;
    const int lane = tid & 31;
    const int wid  = tid >> 5;
    const int g = lane >> 2, t = lane & 3;
    const int qbase = blockIdx.x * 128;
    const int bh    = blockIdx.y;
    const int wq    = wid * 16;

    // --- Stage Q row-major (tf32) into transient area ---
    const float* Qp = g_Q + ((size_t)bh * S_ + qbase) * D_;
#pragma unroll
    for (int it = 0; it < 8; it++) {
        int idx = tid + it * 256;
        int row = idx >> 4, c4 = (idx & 15) * 4;
        *(float4*)&Qtmp[row * 68 + c4] =
            to_tf32_4(*(const float4*)(Qp + (size_t)row * D_ + c4));
    }
    __syncthreads();

    // --- Convert to fragment-major Qf (reads conflict-free: bank 4g+t) ---
#pragma unroll
    for (int ks = 0; ks < 8; ks++) {
        float q0 = Qtmp[(wq + g) * 68 + ks * 8 + t];
        float q1 = Qtmp[(wq + g + 8) * 68 + ks * 8 + t];
        float q2 = Qtmp[(wq + g) * 68 + ks * 8 + t + 4];
        float q3 = Qtmp[(wq + g + 8) * 68 + ks * 8 + t + 4];
        float4 f = { q0, q1, q2, q3 };
        *(float4*)&Qf[wid * 1024 + ks * 128 + lane * 4] = f;
    }
    __syncthreads();   // Qtmp dead; Kf/Vf may be written from here on

    float m0r = -INFINITY, m1r = -INFINITY, l0 = 0.0f, l1 = 0.0f;
    float oacc[8][4];
#pragma unroll
    for (int nt = 0; nt < 8; nt++)
#pragma unroll
        for (int r = 0; r < 4; r++) oacc[nt][r] = 0.0f;

    const int* mrow0 = mask + ((size_t)bh * S_ + (qbase + wq + g)) * S_;
    const int* mrow1 = mrow0 + 8 * S_;

    // V staging map (fixed per thread)
    const int vrp = tid >> 3, vc = tid & 7;
    const int vks = vrp >> 2, vt = vrp & 3, vr = vks * 8 + vt;

    for (int kt = 0; kt < 16; kt++) {
        const int kbase = kt * 64;

        // Mask prefetch for this tile (latency covered by staging + QK MMAs)
        int2 mk0[8], mk1[8];
#pragma unroll
        for (int nt = 0; nt < 8; nt++) {
            mk0[nt] = *(const int2*)&mrow0[kbase + nt * 8 + 2 * t];
            mk1[nt] = *(const int2*)&mrow1[kbase + nt * 8 + 2 * t];
        }

        // --- Stage K in fragment-pair order: 2 items/thread ---
#pragma unroll
        for (int it = 0; it < 2; it++) {
            int item = tid + it * 256;          // 0..511
            int r = item >> 3, c = item & 7;
            const float* gk = g_K + ((size_t)bh * S_ + kbase + r) * D_ + c * 8;
            float4 v0 = to_tf32_4(*(const float4*)gk);
            float4 v1 = to_tf32_4(*(const float4*)(gk + 4));
            float* dst = Kf + ((r >> 3) * 8 + c) * 68 + (r & 7) * 8;
            float4 w0 = { v0.x, v1.x, v0.y, v1.y };
            float4 w1 = { v0.z, v1.z, v0.w, v1.w };
            *(float4*)(dst)     = w0;
            *(float4*)(dst + 4) = w1;
        }
        // --- Stage V: row pair (vr, vr+4), 8-col block vc ---
        {
            const float* gv = g_V + ((size_t)bh * S_ + kbase + vr) * D_ + vc * 8;
            float4 a0 = to_tf32_4(*(const float4*)gv);
            float4 a1 = to_tf32_4(*(const float4*)(gv + 4));
            float4 b0 = to_tf32_4(*(const float4*)(gv + 4 * D_));
            float4 b1 = to_tf32_4(*(const float4*)(gv + 4 * D_ + 4));
            float* dst = Vf + (vks * 8 + vc) * 68 + vt * 2;
            float2 p;
            p.x = a0.x; p.y = b0.x; *(float2*)(dst + 0)  = p;
            p.x = a0.y; p.y = b0.y; *(float2*)(dst + 8)  = p;
            p.x = a0.z; p.y = b0.z; *(float2*)(dst + 16) = p;
            p.x = a0.w; p.y = b0.w; *(float2*)(dst + 24) = p;
            p.x = a1.x; p.y = b1.x; *(float2*)(dst + 32) = p;
            p.x = a1.y; p.y = b1.y; *(float2*)(dst + 40) = p;
            p.x = a1.z; p.y = b1.z; *(float2*)(dst + 48) = p;
            p.x = a1.w; p.y = b1.w; *(float2*)(dst + 56) = p;
        }
        __syncthreads();

        // --- S = Q @ K^T : LDS.128 A-frags, LDS.64 B-frags ---
        float sacc[8][4];
#pragma unroll
        for (int nt = 0; nt < 8; nt++)
#pragma unroll
            for (int r = 0; r < 4; r++) sacc[nt][r] = 0.0f;
#pragma unroll
        for (int ks = 0; ks < 8; ks++) {
            uint4 qf = *(const uint4*)&Qf[wid * 1024 + ks * 128 + lane * 4];
            uint32_t qa_[4] = { qf.x, qf.y, qf.z, qf.w };
#pragma unroll
            for (int nt = 0; nt < 8; nt++) {
                float2 kf = *(const float2*)&Kf[(nt * 8 + ks) * 68 + lane * 2];
                mma_tf32(sacc[nt], qa_, fbits(kf.x), fbits(kf.y));
            }
        }

        // --- Mask + exp2-scale, row maxima ---
        float rm0 = -INFINITY, rm1 = -INFINITY;
#pragma unroll
        for (int nt = 0; nt < 8; nt++) {
            sacc[nt][0] = mk0[nt].x ? sacc[nt][0] * SCL : -INFINITY;
            sacc[nt][1] = mk0[nt].y ? sacc[nt][1] * SCL : -INFINITY;
            sacc[nt][2] = mk1[nt].x ? sacc[nt][2] * SCL : -INFINITY;
            sacc[nt][3] = mk1[nt].y ? sacc[nt][3] * SCL : -INFINITY;
            rm0 = fmaxf(rm0, fmaxf(sacc[nt][0], sacc[nt][1]));
            rm1 = fmaxf(rm1, fmaxf(sacc[nt][2], sacc[nt][3]));
        }
#pragma unroll
        for (int off = 1; off <= 2; off <<= 1) {
            rm0 = fmaxf(rm0, __shfl_xor_sync(0xffffffffu, rm0, off));
            rm1 = fmaxf(rm1, __shfl_xor_sync(0xffffffffu, rm1, off));
        }
        float mn0 = fmaxf(m0r, rm0);
        float mn1 = fmaxf(m1r, rm1);
        float corr0 = (mn0 == -INFINITY) ? 1.0f : exp2f(m0r - mn0);
        float corr1 = (mn1 == -INFINITY) ? 1.0f : exp2f(m1r - mn1);
        m0r = mn0; m1r = mn1;

        // --- exp2, write P in fragment-major order, row sums ---
        const int La  = g * 4 + ((2 * t) & 3);
        const int Lb  = g * 4 + ((2 * t + 1) & 3);
        const int pof = (t < 2) ? 0 : 2;     // float offset within frag slot
        float* pwb = Pf + wid * 1024;
        float rs0 = 0.0f, rs1 = 0.0f;
#pragma unroll
        for (int nt = 0; nt < 8; nt++) {
            float p0 = (sacc[nt][0] == -INFINITY) ? 0.0f : exp2f(sacc[nt][0] - mn0);
            float p1 = (sacc[nt][1] == -INFINITY) ? 0.0f : exp2f(sacc[nt][1] - mn0);
            float p2 = (sacc[nt][2] == -INFINITY) ? 0.0f : exp2f(sacc[nt][2] - mn1);
            float p3 = (sacc[nt][3] == -INFINITY) ? 0.0f : exp2f(sacc[nt][3] - mn1);
            rs0 += p0 + p1;  rs1 += p2 + p3;
            float2 wa = { p0, p2 }, wb = { p1, p3 };
            *(float2*)&pwb[nt * 128 + La * 4 + pof] = wa;
            *(float2*)&pwb[nt * 128 + Lb * 4 + pof] = wb;
        }
#pragma unroll
        for (int off = 1; off <= 2; off <<= 1) {
            rs0 += __shfl_xor_sync(0xffffffffu, rs0, off);
            rs1 += __shfl_xor_sync(0xffffffffu, rs1, off);
        }
        l0 = l0 * corr0 + rs0;
        l1 = l1 * corr1 + rs1;
#pragma unroll
        for (int nt = 0; nt < 8; nt++) {
            oacc[nt][0] *= corr0; oacc[nt][1] *= corr0;
            oacc[nt][2] *= corr1; oacc[nt][3] *= corr1;
        }
        __syncwarp();   // Pf region is warp-private: order STS -> LDS

        // --- O += P @ V ---
#pragma unroll
        for (int ks = 0; ks < 8; ks++) {
            uint4 pf = *(const uint4*)&Pf[wid * 1024 + ks * 128 + lane * 4];
            uint32_t pa_[4] = { pf.x, pf.y, pf.z, pf.w };
#pragma unroll
            for (int nt = 0; nt < 8; nt++) {
                float2 vf = *(const float2*)&Vf[(ks * 8 + nt) * 68 + lane * 2];
                mma_tf32(oacc[nt], pa_, fbits(vf.x), fbits(vf.y));
            }
        }
        __syncthreads();   // Kf/Vf reads done before next tile's staging
    }

    // --- Final normalize + write [b*s][h*64+d] ---
    const int b = bh >> 4;
    const int h = bh & 15;
    const int r0 = qbase + wq + g;
    float inv0 = 1.0f / l0, inv1 = 1.0f / l1;
#pragma unroll
    for (int nt = 0; nt < 8; nt++) {
        int col = h * D_ + nt * 8 + 2 * t;
        float2 v0 = { oacc[nt][0] * inv0, oacc[nt][1] * inv0 };
        float2 v1 = { oacc[nt][2] * inv1, oacc[nt][3] * inv1 };
        *(float2*)(Og + ((size_t)(b * S_ + r0)) * (H_ * D_) + col)     = v0;
        *(float2*)(Og + ((size_t)(b * S_ + r0 + 8)) * (H_ * D_) + col) = v1;
    }
}

// ---------------------------------------------------------------------------
// Launch
// ---------------------------------------------------------------------------
extern "C" void kernel_launch(void* const* d_in, const int* in_sizes, int n_in,
                              void* d_out, int out_size)
{
    const float* input  = (const float*)d_in[0];
    const float* latent = (const float*)d_in[1];
    const int*   mask   = (const int*)d_in[2];
    const float* Wq = (const float*)d_in[3];
    const float* bq = (const float*)d_in[4];
    const float* Wk = (const float*)d_in[5];
    const float* bk = (const float*)d_in[6];
    const float* Wv = (const float*)d_in[7];
    const float* bv = (const float*)d_in[8];
    const float* Wo = (const float*)d_in[9];
    const float* bo = (const float*)d_in[10];
    float* out = (float*)d_out;

    float *qp, *kp, *vp, *op;
    cudaGetSymbolAddress((void**)&qp, g_Q);
    cudaGetSymbolAddress((void**)&kp, g_K);
    cudaGetSymbolAddress((void**)&vp, g_V);
    cudaGetSymbolAddress((void**)&op, g_O);

    cudaFuncSetAttribute(attn_mma_kernel,
                         cudaFuncAttributeMaxDynamicSharedMemorySize, ATTN_SMEM);

    dim3 gg(LAT_ / 128, (B_ * S_) / 128);   // (8, 64)
    gemm_mma<1><<<gg, 256>>>(latent, Wq, bq, qp);
    gemm_mma<1><<<gg, 256>>>(input,  Wk, bk, kp);
    gemm_mma<1><<<gg, 256>>>(input,  Wv, bv, vp);

    dim3 ga(S_ / 128, B_ * H_);             // (8, 128)
    attn_mma_kernel<<<ga, 256, ATTN_SMEM>>>(mask, op);

    gemm_mma<0><<<gg, 256>>>(op, Wo, bo, out);
}